// round 11
// baseline (speedup 1.0000x reference)
#include <cuda_runtime.h>
#include <cuda_bf16.h>

// Problem constants (fixed dataset shapes)
#define NMAX 100000
#define EMAX 1600000

// -------- scratch (static device globals; no dynamic allocation) --------
__device__ int g_count[NMAX];     // per-node edge count (histogram)
__device__ int g_off[NMAX];       // start offset per node (contiguous, unordered)
__device__ int g_rank[EMAX];      // per-edge rank within its destination node
__device__ int g_col[EMAX];       // CSR: source/col node per edge (grouped by dest)
__device__ int g_total;           // atomic base for block-ordered offset assignment

// -------- kernel 0: zero histogram + total (int4 stores) --------
__global__ void zero_counts(int n4) {
    int i = blockIdx.x * blockDim.x + threadIdx.x;
    if (i < n4) ((int4*)g_count)[i] = make_int4(0, 0, 0, 0);
    if (i == 0) g_total = 0;
}

// -------- kernel 1: histogram + per-edge rank (8 edges/thread) --------
__global__ void hist_kernel(const int* __restrict__ ind, int E) {
    int t = blockIdx.x * blockDim.x + threadIdx.x;
    int e = t * 8;
    if (e + 7 < E) {
        int4 dA = *(const int4*)(ind + e);
        int4 dB = *(const int4*)(ind + e + 4);
        int4 rA, rB;
        rA.x = atomicAdd(&g_count[dA.x], 1);
        rA.y = atomicAdd(&g_count[dA.y], 1);
        rA.z = atomicAdd(&g_count[dA.z], 1);
        rA.w = atomicAdd(&g_count[dA.w], 1);
        rB.x = atomicAdd(&g_count[dB.x], 1);
        rB.y = atomicAdd(&g_count[dB.y], 1);
        rB.z = atomicAdd(&g_count[dB.z], 1);
        rB.w = atomicAdd(&g_count[dB.w], 1);
        *(int4*)(g_rank + e)     = rA;
        *(int4*)(g_rank + e + 4) = rB;
    } else {
        for (; e < E; e++) g_rank[e] = atomicAdd(&g_count[ind[e]], 1);
    }
}

// -------- kernel 2: warp-shuffle exclusive scan + atomic block base --------
__global__ void scan_atomic(int n) {
    __shared__ int wsum[32];
    __shared__ int base;
    int t = threadIdx.x, lane = t & 31, w = t >> 5;
    int i = blockIdx.x * 1024 + t;
    int vv = (i < n) ? g_count[i] : 0;

    int x = vv;                                     // inclusive warp scan
    #pragma unroll
    for (int o = 1; o < 32; o <<= 1) {
        int y = __shfl_up_sync(0xFFFFFFFFu, x, o);
        if (lane >= o) x += y;
    }
    if (lane == 31) wsum[w] = x;
    __syncthreads();
    if (w == 0) {                                   // scan the 32 warp sums
        int s = wsum[lane];
        #pragma unroll
        for (int o = 1; o < 32; o <<= 1) {
            int y = __shfl_up_sync(0xFFFFFFFFu, s, o);
            if (lane >= o) s += y;
        }
        wsum[lane] = s;                             // inclusive
        if (lane == 31) base = atomicAdd(&g_total, s);  // s = block total
    }
    __syncthreads();
    int wbase = (w > 0) ? wsum[w - 1] : 0;
    if (i < n) g_off[i] = x - vv + wbase + base;    // exclusive + block base
}

// -------- kernel 3: atomic-free CSR scatter (8 edges/thread) --------
__global__ void scatter_kernel(const int* __restrict__ ind, int E) {
    int t = blockIdx.x * blockDim.x + threadIdx.x;
    int e = t * 8;
    if (e + 7 < E) {
        int4 dA = *(const int4*)(ind + e);
        int4 dB = *(const int4*)(ind + e + 4);
        int4 sA = *(const int4*)(ind + E + e);
        int4 sB = *(const int4*)(ind + E + e + 4);
        int4 rA = *(const int4*)(g_rank + e);
        int4 rB = *(const int4*)(g_rank + e + 4);
        g_col[g_off[dA.x] + rA.x] = sA.x;
        g_col[g_off[dA.y] + rA.y] = sA.y;
        g_col[g_off[dA.z] + rA.z] = sA.z;
        g_col[g_off[dA.w] + rA.w] = sA.w;
        g_col[g_off[dB.x] + rB.x] = sB.x;
        g_col[g_off[dB.y] + rB.y] = sB.y;
        g_col[g_off[dB.z] + rB.z] = sB.z;
        g_col[g_off[dB.w] + rB.w] = sB.w;
    } else {
        for (; e < E; e++)
            g_col[g_off[ind[e]] + g_rank[e]] = ind[E + e];
    }
}

// -------- kernel 4: fused logits + softmax + SpMM, warp per node --------
// Single fused per-lane partial: z = (0.125*q)·k + (e^λ*eig)·eig → ONE
// 5-step butterfly per edge. float2 loads, unroll-by-2 for SHFL overlap.
__global__ void node_fused(const float2* __restrict__ q2,
                           const float2* __restrict__ k2,
                           const float*  __restrict__ eigs,
                           const float2* __restrict__ v2,
                           const float*  __restrict__ lambda0,
                           float2* __restrict__ out2,
                           int n) {
    int gw   = (blockIdx.x * blockDim.x + threadIdx.x) >> 5;
    int lane = threadIdx.x & 31;
    if (gw >= n) return;

    int beg = g_off[gw];
    int cnt = g_count[gw];

    float2 qv = q2[(size_t)gw * 32 + lane];
    float q0s = qv.x * 0.125f;                      // fold 1/sqrt(64)
    float q1s = qv.y * 0.125f;
    float egl = expf(lambda0[0]) * eigs[(size_t)gw * 32 + lane];  // fold e^λ

    float ax = 0.0f, ay = 0.0f, denom = 0.0f;
    int j = 0;
    for (; j + 1 < cnt; j += 2) {
        int col0 = g_col[beg + j];
        int col1 = g_col[beg + j + 1];
        size_t b0 = (size_t)col0 * 32 + lane;
        size_t b1 = (size_t)col1 * 32 + lane;
        float2 kA = k2[b0], kB = k2[b1];
        float  eA = eigs[b0], eB = eigs[b1];
        float2 vA = v2[b0], vB = v2[b1];

        float z0 = q0s * kA.x + q1s * kA.y + egl * eA;
        float z1 = q0s * kB.x + q1s * kB.y + egl * eB;
        #pragma unroll
        for (int o = 16; o; o >>= 1) {              // two independent chains
            z0 += __shfl_xor_sync(0xFFFFFFFFu, z0, o);
            z1 += __shfl_xor_sync(0xFFFFFFFFu, z1, o);
        }
        float ev0 = fminf(expf(z0), 5.0f);          // clip(exp,-5,5); exp > 0
        float ev1 = fminf(expf(z1), 5.0f);

        denom += ev0 + ev1;
        ax += ev0 * vA.x + ev1 * vB.x;
        ay += ev0 * vA.y + ev1 * vB.y;
    }
    if (j < cnt) {                                  // odd tail
        int col = g_col[beg + j];
        size_t b = (size_t)col * 32 + lane;
        float2 kA = k2[b];
        float  eA = eigs[b];
        float2 vA = v2[b];
        float z = q0s * kA.x + q1s * kA.y + egl * eA;
        #pragma unroll
        for (int o = 16; o; o >>= 1)
            z += __shfl_xor_sync(0xFFFFFFFFu, z, o);
        float ev = fminf(expf(z), 5.0f);
        denom += ev;
        ax += ev * vA.x;
        ay += ev * vA.y;
    }

    float inv = (cnt > 0) ? (1.0f / denom) : 0.0f;  // denom==0 only if cnt==0
    float2 r; r.x = ax * inv; r.y = ay * inv;
    out2[(size_t)gw * 32 + lane] = r;
}

extern "C" void kernel_launch(void* const* d_in, const int* in_sizes, int n_in,
                              void* d_out, int out_size) {
    const float2* q2   = (const float2*)d_in[0];
    const float2* k2   = (const float2*)d_in[1];
    const float2* v2   = (const float2*)d_in[2];
    const float*  eigs = (const float*)d_in[3];
    const float*  l0   = (const float*)d_in[4];
    const int*    ind  = (const int*)d_in[5];
    float2*       out2 = (float2*)d_out;

    int n  = in_sizes[0] / 64;    // 100000
    int E  = in_sizes[5] / 2;     // 1600000
    int nb = (n + 1023) / 1024;
    int n4 = (n + 3) / 4;         // int4 zero threads
    int t8 = (E + 7) / 8;         // threads for 8-edge kernels

    zero_counts<<<(n4 + 255) / 256, 256>>>(n4);
    hist_kernel<<<(t8 + 255) / 256, 256>>>(ind, E);
    scan_atomic<<<nb, 1024>>>(n);
    scatter_kernel<<<(t8 + 255) / 256, 256>>>(ind, E);
    node_fused<<<(n + 7) / 8, 256>>>(q2, k2, eigs, v2, l0, out2, n);
}